// round 2
// baseline (speedup 1.0000x reference)
#include <cuda_runtime.h>
#include <cuda_bf16.h>
#include <cstdint>

// ============================================================================
// Problem constants
// ============================================================================
#define NROWS 16384
#define DDIM  128
#define TILE  128

static __device__ __nv_bfloat16 g_Abf[NROWS * DDIM];
static __device__ __nv_bfloat16 g_Pbf[NROWS * DDIM];
static __device__ float g_partS[2 * NROWS];   // per-row expsum partials (2 col halves)
static __device__ float g_diagv[NROWS];
static __device__ float g_acc;

#define INV_T   14.285714285714286f
#define C_EXP   20.609929155556620f   // log2(e) / 0.07

// SMEM: A tile @0 (128 x 272B), B0 @34816, B1 @69632
#define ROWB   272
#define A_OFF  0
#define B_OFF  34816
#define TILE_BYTES 34816
#define SMEM_TOTAL (3 * 34816)

// ============================================================================
// PTX helpers (portable: sm_80+ only, no arch-accelerated features)
// ============================================================================
__device__ __forceinline__ uint32_t smem_to_u32(const void* p) {
    uint32_t a;
    asm("{ .reg .u64 t; cvta.to.shared.u64 t, %1; cvt.u32.u64 %0, t; }" : "=r"(a) : "l"(p));
    return a;
}
__device__ __forceinline__ float ex2f_fast(float x) {
    float y; asm("ex2.approx.ftz.f32 %0, %1;" : "=f"(y) : "f"(x)); return y;
}

#define LDSM_X4(r0, r1, r2, r3, addr) \
    asm volatile("ldmatrix.sync.aligned.m8n8.x4.shared.b16 {%0,%1,%2,%3}, [%4];" \
        : "=r"(r0), "=r"(r1), "=r"(r2), "=r"(r3) : "r"(addr))

#define MMA_BF16(d, a, b0, b1) \
    asm volatile("mma.sync.aligned.m16n8k16.row.col.f32.bf16.bf16.f32 " \
        "{%0,%1,%2,%3},{%4,%5,%6,%7},{%8,%9},{%0,%1,%2,%3};" \
        : "+f"((d)[0]), "+f"((d)[1]), "+f"((d)[2]), "+f"((d)[3]) \
        : "r"((a)[0]), "r"((a)[1]), "r"((a)[2]), "r"((a)[3]), "r"(b0), "r"(b1))

#define CP_ASYNC16(saddr, gptr) \
    asm volatile("cp.async.cg.shared.global [%0], [%1], 16;" :: "r"(saddr), "l"(gptr))
#define CP_COMMIT() asm volatile("cp.async.commit_group;")
#define CP_WAIT0()  asm volatile("cp.async.wait_group 0;")
#define CP_WAIT1()  asm volatile("cp.async.wait_group 1;")

// ============================================================================
// Kernel 1: normalize rows (fp32) -> bf16, zero accumulator
// ============================================================================
__global__ void __launch_bounds__(256) normalize_kernel(const float* __restrict__ A,
                                                        const float* __restrict__ P) {
    if (blockIdx.x == 0 && threadIdx.x == 0) g_acc = 0.0f;
    int warp = (blockIdx.x * blockDim.x + threadIdx.x) >> 5;
    int lane = threadIdx.x & 31;
    if (warp >= 2 * NROWS) return;
    const float* src;
    __nv_bfloat16* dst;
    if (warp < NROWS) { src = A + (size_t)warp * DDIM; dst = g_Abf + (size_t)warp * DDIM; }
    else { int r = warp - NROWS; src = P + (size_t)r * DDIM; dst = g_Pbf + (size_t)r * DDIM; }
    float4 v = reinterpret_cast<const float4*>(src)[lane];
    float ss = v.x * v.x + v.y * v.y + v.z * v.z + v.w * v.w;
    #pragma unroll
    for (int o = 16; o > 0; o >>= 1) ss += __shfl_xor_sync(0xFFFFFFFFu, ss, o);
    float s = 1.0f / fmaxf(sqrtf(ss), 1e-12f);
    __nv_bfloat162 h0 = __floats2bfloat162_rn(v.x * s, v.y * s);
    __nv_bfloat162 h1 = __floats2bfloat162_rn(v.z * s, v.w * s);
    reinterpret_cast<__nv_bfloat162*>(dst)[lane * 2 + 0] = h0;
    reinterpret_cast<__nv_bfloat162*>(dst)[lane * 2 + 1] = h1;
}

// ============================================================================
// cp.async loader: one 128x128 bf16 tile (row-major) -> padded SMEM (272B rows)
// ============================================================================
__device__ __forceinline__ void cp_tile(uint32_t sbase, const __nv_bfloat16* gsrc, int tid) {
    const char* g = reinterpret_cast<const char*>(gsrc);
    #pragma unroll
    for (int i = 0; i < 8; i++) {
        int idx = tid + i * 256;          // 2048 chunks of 16B
        int row = idx >> 4;
        int c   = idx & 15;
        uint32_t s = sbase + row * ROWB + c * 16;
        CP_ASYNC16(s, g + idx * 16);
    }
}

// ============================================================================
// Kernel 2: fused GEMM + exp rowsum + diag.
// grid = (128 row-blocks, 2 column halves), 256 threads, 2 CTAs/SM.
// Each warp owns 16 rows; A fragments register-resident for the whole CTA life.
// ============================================================================
__global__ void __launch_bounds__(256, 2) infonce_main_kernel() {
    extern __shared__ char smem[];
    uint32_t sb = smem_to_u32(smem);
    int tid = threadIdx.x;
    int lane = tid & 31;
    int w = tid >> 5;
    int rb = blockIdx.x;        // row block (0..127)
    int ch = blockIdx.y;        // column half (0..1)
    int gt0 = ch * 64;          // first column tile

    // Load A tile + first B tile
    cp_tile(sb + A_OFF, g_Abf + (size_t)rb * TILE * DDIM, tid);
    CP_COMMIT();
    cp_tile(sb + B_OFF, g_Pbf + (size_t)gt0 * TILE * DDIM, tid);
    CP_COMMIT();
    CP_WAIT0();
    __syncthreads();

    // A fragments: 8 k-steps x 4 regs, loaded once
    uint32_t afrag[8][4];
    {
        uint32_t a_addr = sb + A_OFF + (w * 16 + (lane & 15)) * ROWB + (lane >> 4) * 16;
        #pragma unroll
        for (int k = 0; k < 8; k++)
            LDSM_X4(afrag[k][0], afrag[k][1], afrag[k][2], afrag[k][3], a_addr + k * 32);
    }

    int g = lane >> 2;
    int tig = lane & 3;
    uint32_t b_lane_off = (uint32_t)(((lane & 7) + ((lane >> 4) << 3)) * ROWB
                                     + ((lane >> 3) & 1) * 16);

    float S0 = 0.0f, S1 = 0.0f, d0 = 0.0f, d1 = 0.0f;

    for (int t = 0; t < 64; t++) {
        if (t + 1 < 64) {
            cp_tile(sb + B_OFF + ((t + 1) & 1) * TILE_BYTES,
                    g_Pbf + (size_t)(gt0 + t + 1) * TILE * DDIM, tid);
            CP_COMMIT();
            CP_WAIT1();
        } else {
            CP_WAIT0();
        }
        __syncthreads();

        uint32_t bbase = sb + B_OFF + (t & 1) * TILE_BYTES + b_lane_off;
        int diag_t = (gt0 + t == rb);

        #pragma unroll
        for (int half = 0; half < 2; half++) {
            float acc[8][4];
            #pragma unroll
            for (int p = 0; p < 8; p++) {
                acc[p][0] = 0.0f; acc[p][1] = 0.0f; acc[p][2] = 0.0f; acc[p][3] = 0.0f;
            }
            #pragma unroll
            for (int k = 0; k < 8; k++) {
                #pragma unroll
                for (int pp = 0; pp < 4; pp++) {
                    int nb = half * 8 + pp * 2;
                    uint32_t b0, b1, b2, b3;
                    LDSM_X4(b0, b1, b2, b3, bbase + nb * 8 * ROWB + k * 32);
                    MMA_BF16(acc[pp * 2 + 0], afrag[k], b0, b1);
                    MMA_BF16(acc[pp * 2 + 1], afrag[k], b2, b3);
                }
            }
            // epilogue: exp + running sums (+ diag capture)
            #pragma unroll
            for (int p = 0; p < 8; p++) {
                int colbase = (half * 8 + p) * 8 + tig * 2;
                #pragma unroll
                for (int j = 0; j < 4; j++) {
                    float v = acc[p][j];
                    float e = ex2f_fast(v * C_EXP);
                    int col = colbase + (j & 1);
                    int rloc = w * 16 + g + ((j >> 1) << 3);
                    if (j >> 1) S1 += e; else S0 += e;
                    if (diag_t && col == rloc) { if (j >> 1) d1 = v; else d0 = v; }
                }
            }
        }
        __syncthreads();   // buf[t&1] free for prefetch at t+1
    }

    // reduce across the 4 threads sharing a row (tig dimension)
    S0 += __shfl_xor_sync(0xFFFFFFFFu, S0, 1); S0 += __shfl_xor_sync(0xFFFFFFFFu, S0, 2);
    S1 += __shfl_xor_sync(0xFFFFFFFFu, S1, 1); S1 += __shfl_xor_sync(0xFFFFFFFFu, S1, 2);
    d0 += __shfl_xor_sync(0xFFFFFFFFu, d0, 1); d0 += __shfl_xor_sync(0xFFFFFFFFu, d0, 2);
    d1 += __shfl_xor_sync(0xFFFFFFFFu, d1, 1); d1 += __shfl_xor_sync(0xFFFFFFFFu, d1, 2);

    if (tig == 0) {
        int row0 = rb * TILE + w * 16 + g;
        g_partS[ch * NROWS + row0]     = S0;
        g_partS[ch * NROWS + row0 + 8] = S1;
        if (ch == (rb >> 6)) {         // this column half contains the diagonal
            g_diagv[row0]     = d0;
            g_diagv[row0 + 8] = d1;
        }
    }
}

// ============================================================================
// Kernel 3: per-row loss + global reduction
// ============================================================================
__global__ void __launch_bounds__(256) rowsum_kernel() {
    int row = blockIdx.x * 256 + threadIdx.x;
    float v = logf(g_partS[row] + g_partS[NROWS + row]) - g_diagv[row] * INV_T;
    #pragma unroll
    for (int o = 16; o > 0; o >>= 1) v += __shfl_xor_sync(0xFFFFFFFFu, v, o);
    __shared__ float red[8];
    int lane = threadIdx.x & 31, wid = threadIdx.x >> 5;
    if (lane == 0) red[wid] = v;
    __syncthreads();
    if (wid == 0) {
        float s = (lane < 8) ? red[lane] : 0.0f;
        #pragma unroll
        for (int o = 4; o > 0; o >>= 1) s += __shfl_xor_sync(0xFFFFFFFFu, s, o);
        if (lane == 0) atomicAdd(&g_acc, s);
    }
}

// ============================================================================
// Kernel 4: finalize
// ============================================================================
__global__ void finalize_kernel(float* out) {
    out[0] = g_acc * (1.0f / (float)NROWS);
}

// ============================================================================
// Launch
// ============================================================================
extern "C" void kernel_launch(void* const* d_in, const int* in_sizes, int n_in,
                              void* d_out, int out_size) {
    const float* A = (const float*)d_in[0];
    const float* P = (const float*)d_in[1];
    cudaFuncSetAttribute(infonce_main_kernel,
                         cudaFuncAttributeMaxDynamicSharedMemorySize, SMEM_TOTAL);
    normalize_kernel<<<(2 * NROWS) / 8, 256>>>(A, P);
    dim3 grid(128, 2);
    infonce_main_kernel<<<grid, 256, SMEM_TOTAL>>>();
    rowsum_kernel<<<NROWS / 256, 256>>>();
    finalize_kernel<<<1, 1>>>((float*)d_out);
}

// round 3
// speedup vs baseline: 1.0939x; 1.0939x over previous
#include <cuda_runtime.h>
#include <cuda_bf16.h>
#include <cstdint>

// ============================================================================
// Problem constants
// ============================================================================
#define NROWS 16384
#define DDIM  128
#define TILE  128

static __device__ __nv_bfloat16 g_Abf[NROWS * DDIM];
static __device__ __nv_bfloat16 g_Pbf[NROWS * DDIM];
static __device__ float g_partS[4 * NROWS];   // per-row expsum partials (colhalf x warp-colgroup)
static __device__ float g_diagv[NROWS];
static __device__ float g_acc;

#define INV_T   14.285714285714286f
#define C_EXP   20.609929155556620f   // log2(e) / 0.07

// SMEM: 3 rotating 128x128 bf16 tile buffers (272B padded rows).
// Buffer 2 (@0) initially holds the A tile; reused for B after afrag load.
#define ROWB   272
#define TILE_BYTES 34816
#define SMEM_TOTAL (3 * 34816)

// ============================================================================
// PTX helpers (sm_80+ portable; no arch-accelerated features: ptxas target
// is plain sm_100, so tcgen05/TMEM are unavailable)
// ============================================================================
__device__ __forceinline__ uint32_t smem_to_u32(const void* p) {
    uint32_t a;
    asm("{ .reg .u64 t; cvta.to.shared.u64 t, %1; cvt.u32.u64 %0, t; }" : "=r"(a) : "l"(p));
    return a;
}
__device__ __forceinline__ float ex2f_fast(float x) {
    float y; asm("ex2.approx.ftz.f32 %0, %1;" : "=f"(y) : "f"(x)); return y;
}

#define LDSM_X4(r0, r1, r2, r3, addr) \
    asm volatile("ldmatrix.sync.aligned.m8n8.x4.shared.b16 {%0,%1,%2,%3}, [%4];" \
        : "=r"(r0), "=r"(r1), "=r"(r2), "=r"(r3) : "r"(addr))

#define MMA_BF16(d, a, b0, b1) \
    asm volatile("mma.sync.aligned.m16n8k16.row.col.f32.bf16.bf16.f32 " \
        "{%0,%1,%2,%3},{%4,%5,%6,%7},{%8,%9},{%0,%1,%2,%3};" \
        : "+f"((d)[0]), "+f"((d)[1]), "+f"((d)[2]), "+f"((d)[3]) \
        : "r"((a)[0]), "r"((a)[1]), "r"((a)[2]), "r"((a)[3]), "r"(b0), "r"(b1))

#define CP_ASYNC16(saddr, gptr) \
    asm volatile("cp.async.cg.shared.global [%0], [%1], 16;" :: "r"(saddr), "l"(gptr))
#define CP_COMMIT() asm volatile("cp.async.commit_group;")
#define CP_WAIT1()  asm volatile("cp.async.wait_group 1;")
#define CP_WAIT2()  asm volatile("cp.async.wait_group 2;")

// ============================================================================
// Kernel 1: normalize rows (fp32) -> bf16, zero accumulator
// ============================================================================
__global__ void __launch_bounds__(256) normalize_kernel(const float* __restrict__ A,
                                                        const float* __restrict__ P) {
    if (blockIdx.x == 0 && threadIdx.x == 0) g_acc = 0.0f;
    int warp = (blockIdx.x * blockDim.x + threadIdx.x) >> 5;
    int lane = threadIdx.x & 31;
    if (warp >= 2 * NROWS) return;
    const float* src;
    __nv_bfloat16* dst;
    if (warp < NROWS) { src = A + (size_t)warp * DDIM; dst = g_Abf + (size_t)warp * DDIM; }
    else { int r = warp - NROWS; src = P + (size_t)r * DDIM; dst = g_Pbf + (size_t)r * DDIM; }
    float4 v = reinterpret_cast<const float4*>(src)[lane];
    float ss = v.x * v.x + v.y * v.y + v.z * v.z + v.w * v.w;
    #pragma unroll
    for (int o = 16; o > 0; o >>= 1) ss += __shfl_xor_sync(0xFFFFFFFFu, ss, o);
    float s = 1.0f / fmaxf(sqrtf(ss), 1e-12f);
    __nv_bfloat162 h0 = __floats2bfloat162_rn(v.x * s, v.y * s);
    __nv_bfloat162 h1 = __floats2bfloat162_rn(v.z * s, v.w * s);
    reinterpret_cast<__nv_bfloat162*>(dst)[lane * 2 + 0] = h0;
    reinterpret_cast<__nv_bfloat162*>(dst)[lane * 2 + 1] = h1;
}

// ============================================================================
// cp.async loader: one 128x128 bf16 tile (row-major) -> padded SMEM (272B rows)
// ============================================================================
__device__ __forceinline__ void cp_tile(uint32_t sbase, const __nv_bfloat16* gsrc, int tid) {
    const char* g = reinterpret_cast<const char*>(gsrc);
    #pragma unroll
    for (int i = 0; i < 8; i++) {
        int idx = tid + i * 256;          // 2048 chunks of 16B
        int row = idx >> 4;
        int c   = idx & 15;
        uint32_t s = sbase + row * ROWB + c * 16;
        CP_ASYNC16(s, g + idx * 16);
    }
}

// ============================================================================
// Kernel 2: fused GEMM + exp rowsum + diag.
// grid = (128 row-blocks, 2 column halves), 256 threads, 2 CTAs/SM.
// Warp (wr, wc): wr = warp>>1 row-group (32 rows), wc = warp&1 col-group (64 cols).
// Each LDSM.x4 of B feeds 4 MMAs -> B smem traffic halved vs 1-D warp split.
// 3-buffer cp.async pipeline, ONE __syncthreads per tile.
// ============================================================================
__global__ void __launch_bounds__(256, 2) infonce_main_kernel() {
    extern __shared__ char smem[];
    uint32_t sb = smem_to_u32(smem);
    int tid = threadIdx.x;
    int lane = tid & 31;
    int w = tid >> 5;
    int wr = w >> 1;            // row-group 0..3
    int wc = w & 1;             // col-group 0..1
    int rb = blockIdx.x;        // row block (0..127)
    int ch = blockIdx.y;        // column half (0..1)
    int gt0 = ch * 64;          // first column tile

    const uint32_t bufoff[3] = {TILE_BYTES, 2 * TILE_BYTES, 0};

    // Prologue: A tile -> buf2(@0); B tiles t0 -> buf0, t1 -> buf1
    cp_tile(sb + 0, g_Abf + (size_t)rb * TILE * DDIM, tid);
    CP_COMMIT();
    cp_tile(sb + bufoff[0], g_Pbf + (size_t)gt0 * TILE * DDIM, tid);
    CP_COMMIT();
    cp_tile(sb + bufoff[1], g_Pbf + (size_t)(gt0 + 1) * TILE * DDIM, tid);
    CP_COMMIT();
    CP_WAIT2();                  // A done (B t0,t1 may still be in flight)
    __syncthreads();

    // A fragments: 8 k-steps x 2 m16-frags x 4 regs, resident for CTA lifetime
    uint32_t afrag[8][2][4];
    {
        #pragma unroll
        for (int f = 0; f < 2; f++) {
            uint32_t a_addr = sb + (wr * 32 + f * 16 + (lane & 15)) * ROWB + (lane >> 4) * 16;
            #pragma unroll
            for (int k = 0; k < 8; k++)
                LDSM_X4(afrag[k][f][0], afrag[k][f][1], afrag[k][f][2], afrag[k][f][3],
                        a_addr + k * 32);
        }
    }
    // (no sync needed: iter-0's barrier orders these loads before any buf2 overwrite)

    int g = lane >> 2;
    int tig = lane & 3;
    uint32_t b_lane_off = (uint32_t)(((lane & 7) + ((lane >> 4) << 3)) * ROWB
                                     + ((lane >> 3) & 1) * 16)
                          + (uint32_t)(wc * 64) * ROWB;

    float S[4] = {0.f, 0.f, 0.f, 0.f};
    float d[4] = {0.f, 0.f, 0.f, 0.f};

    int curbuf = 0, nxtbuf = 2;  // buf for tile t, buf for tile t+2

    for (int t = 0; t < 64; t++) {
        CP_WAIT1();              // tile t's group complete (t+1 may pend)
        __syncthreads();         // t visible to all; all warps done with buf[nxtbuf]'s old data
        if (t + 2 < 64)
            cp_tile(sb + bufoff[nxtbuf], g_Pbf + (size_t)(gt0 + t + 2) * TILE * DDIM, tid);
        CP_COMMIT();             // always commit to keep group counts aligned

        uint32_t bbase = sb + bufoff[curbuf] + b_lane_off;
        int diag_t = (gt0 + t == rb);

        #pragma unroll
        for (int c = 0; c < 4; c++) {
            float acc[2][2][4];
            #pragma unroll
            for (int f = 0; f < 2; f++)
                #pragma unroll
                for (int nb = 0; nb < 2; nb++)
                    #pragma unroll
                    for (int j = 0; j < 4; j++) acc[f][nb][j] = 0.0f;

            uint32_t bchunk = bbase + (uint32_t)(c * 16) * ROWB;
            #pragma unroll
            for (int k = 0; k < 8; k++) {
                uint32_t b0, b1, b2, b3;
                LDSM_X4(b0, b1, b2, b3, bchunk + k * 32);
                MMA_BF16(acc[0][0], afrag[k][0], b0, b1);
                MMA_BF16(acc[0][1], afrag[k][0], b2, b3);
                MMA_BF16(acc[1][0], afrag[k][1], b0, b1);
                MMA_BF16(acc[1][1], afrag[k][1], b2, b3);
            }
            // epilogue: exp + running row sums (+ diag capture)
            #pragma unroll
            for (int f = 0; f < 2; f++) {
                #pragma unroll
                for (int nb = 0; nb < 2; nb++) {
                    #pragma unroll
                    for (int j = 0; j < 4; j++) {
                        float v = acc[f][nb][j];
                        int hi = j >> 1;
                        S[f * 2 + hi] += ex2f_fast(v * C_EXP);
                        if (diag_t) {
                            int col_local = wc * 64 + c * 16 + nb * 8 + tig * 2 + (j & 1);
                            int row_local = wr * 32 + f * 16 + hi * 8 + g;
                            if (col_local == row_local) d[f * 2 + hi] = v;
                        }
                    }
                }
            }
        }
        if (++curbuf == 3) curbuf = 0;
        if (++nxtbuf == 3) nxtbuf = 0;
    }

    // reduce across the 4 threads sharing each row (tig dimension)
    #pragma unroll
    for (int i = 0; i < 4; i++) {
        S[i] += __shfl_xor_sync(0xFFFFFFFFu, S[i], 1);
        S[i] += __shfl_xor_sync(0xFFFFFFFFu, S[i], 2);
        d[i] += __shfl_xor_sync(0xFFFFFFFFu, d[i], 1);
        d[i] += __shfl_xor_sync(0xFFFFFFFFu, d[i], 2);
    }

    if (tig == 0) {
        int part = ch * 2 + wc;
        int wrote_diag = (ch == (rb >> 6)) && ((wr >> 1) == wc);
        #pragma unroll
        for (int i = 0; i < 4; i++) {
            int row_local = wr * 32 + (i >> 1) * 16 + (i & 1) * 8 + g;
            int row = rb * TILE + row_local;
            g_partS[part * NROWS + row] = S[i];
            if (wrote_diag) g_diagv[row] = d[i];
        }
    }
}

// ============================================================================
// Kernel 3: per-row loss + global reduction
// ============================================================================
__global__ void __launch_bounds__(256) rowsum_kernel() {
    int row = blockIdx.x * 256 + threadIdx.x;
    float Ssum = g_partS[row] + g_partS[NROWS + row]
               + g_partS[2 * NROWS + row] + g_partS[3 * NROWS + row];
    float v = logf(Ssum) - g_diagv[row] * INV_T;
    #pragma unroll
    for (int o = 16; o > 0; o >>= 1) v += __shfl_xor_sync(0xFFFFFFFFu, v, o);
    __shared__ float red[8];
    int lane = threadIdx.x & 31, wid = threadIdx.x >> 5;
    if (lane == 0) red[wid] = v;
    __syncthreads();
    if (wid == 0) {
        float s = (lane < 8) ? red[lane] : 0.0f;
        #pragma unroll
        for (int o = 4; o > 0; o >>= 1) s += __shfl_xor_sync(0xFFFFFFFFu, s, o);
        if (lane == 0) atomicAdd(&g_acc, s);
    }
}

// ============================================================================
// Kernel 4: finalize
// ============================================================================
__global__ void finalize_kernel(float* out) {
    out[0] = g_acc * (1.0f / (float)NROWS);
}

// ============================================================================
// Launch
// ============================================================================
extern "C" void kernel_launch(void* const* d_in, const int* in_sizes, int n_in,
                              void* d_out, int out_size) {
    const float* A = (const float*)d_in[0];
    const float* P = (const float*)d_in[1];
    cudaFuncSetAttribute(infonce_main_kernel,
                         cudaFuncAttributeMaxDynamicSharedMemorySize, SMEM_TOTAL);
    normalize_kernel<<<(2 * NROWS) / 8, 256>>>(A, P);
    dim3 grid(128, 2);
    infonce_main_kernel<<<grid, 256, SMEM_TOTAL>>>();
    rowsum_kernel<<<NROWS / 256, 256>>>();
    finalize_kernel<<<1, 1>>>((float*)d_out);
}